// round 8
// baseline (speedup 1.0000x reference)
#include <cuda_runtime.h>
#include <cuda_bf16.h>
#include <cstdint>

// Problem shapes
#define Nrows 16384
#define Hd    512
#define Gg    2
#define Vv    320
#define Dd    256
#define GVc   640

// ---------------------------------------------------------------------------
// Device scratch
// ---------------------------------------------------------------------------
__device__ float g_logits[(size_t)Nrows * GVc];                 // 41.9 MB
__device__ __nv_bfloat16 g_Wt_hi[(size_t)GVc * Hd];             // 0.65 MB
__device__ __nv_bfloat16 g_Wt_lo[(size_t)GVc * Hd];
__device__ float g_acc[GVc];

// ---------------------------------------------------------------------------
// Helpers (baseline ISA only)
// ---------------------------------------------------------------------------
__device__ __forceinline__ uint32_t smem_u32(const void* p) {
    uint32_t a;
    asm("{ .reg .u64 t; cvta.to.shared.u64 t, %1; cvt.u32.u64 %0, t; }" : "=r"(a) : "l"(p));
    return a;
}
#define CP_ASYNC16(dst, src) \
    asm volatile("cp.async.cg.shared.global [%0], [%1], 16;" :: "r"(dst), "l"(src) : "memory")
#define CP_COMMIT() asm volatile("cp.async.commit_group;" ::: "memory")
#define CP_WAIT2()  asm volatile("cp.async.wait_group 2;" ::: "memory")
#define CP_WAIT0()  asm volatile("cp.async.wait_group 0;" ::: "memory")

#define LDSM_X4(r0, r1, r2, r3, a) \
    asm volatile("ldmatrix.sync.aligned.m8n8.x4.shared.b16 {%0,%1,%2,%3}, [%4];" \
        : "=r"(r0), "=r"(r1), "=r"(r2), "=r"(r3) : "r"(a))

#define MMA_BF16(c, a, b) \
    asm volatile("mma.sync.aligned.m16n8k16.row.col.f32.bf16.bf16.f32 " \
        "{%0,%1,%2,%3}, {%4,%5,%6,%7}, {%8,%9}, {%0,%1,%2,%3};" \
        : "+f"((c)[0]), "+f"((c)[1]), "+f"((c)[2]), "+f"((c)[3]) \
        : "r"((a)[0]), "r"((a)[1]), "r"((a)[2]), "r"((a)[3]), "r"((b)[0]), "r"((b)[1]))

#define SW64(o)  ((o) ^ (((o) >> 3) & 0x30))
#define SW128(o) ((o) ^ (((o) >> 3) & 0x70))

__device__ __forceinline__ void split2(float x, float y, uint32_t& hi, uint32_t& lo) {
    __nv_bfloat16 hx = __float2bfloat16_rn(x);
    __nv_bfloat16 hy = __float2bfloat16_rn(y);
    __nv_bfloat162 h2; h2.x = hx; h2.y = hy;
    __nv_bfloat162 l2;
    l2.x = __float2bfloat16_rn(x - __bfloat162float(hx));
    l2.y = __float2bfloat16_rn(y - __bfloat162float(hy));
    hi = *reinterpret_cast<uint32_t*>(&h2);
    lo = *reinterpret_cast<uint32_t*>(&l2);
}

// ---------------------------------------------------------------------------
// Prep: zero g_acc; transpose + split W [512,640] -> Wt_hi/lo [640,512]
// ---------------------------------------------------------------------------
__global__ __launch_bounds__(256) void prep_W(const float* __restrict__ W) {
    int idx = blockIdx.x * 256 + threadIdx.x;        // 0..327679
    if (idx < GVc) g_acc[idx] = 0.0f;
    float x = W[idx];
    int k = idx / GVc, n = idx % GVc;
    __nv_bfloat16 h = __float2bfloat16_rn(x);
    float r = x - __bfloat162float(h);
    g_Wt_hi[(size_t)n * Hd + k] = h;
    g_Wt_lo[(size_t)n * Hd + k] = __float2bfloat16_rn(r);
}

// ---------------------------------------------------------------------------
// bf16x3 GEMM with in-kernel A split: logits = A(f32) @ W + bias
// 128x64 CTA tile, BK=32, 4-stage cp.async (A as f32), SW swizzles, 2 CTAs/SM.
// Per chunk: A f32 arrives in stage (16KB), threads read f32, split hi/lo,
// store bf16 over the same 16KB, then ldmatrix/MMA (round-5 loop shape).
// ---------------------------------------------------------------------------
#define NSTAGE 4
#define NCHUNK 16
#define STAGE_BYTES 24576
#define AF_OFF  0          // f32 A tile (16KB), becomes AHI(0..8K) + ALO(8..16K)
#define AHI_OFF 0
#define ALO_OFF 8192
#define BHI_OFF 16384
#define BLO_OFF 20480
#define GEMM_SMEM (NSTAGE * STAGE_BYTES + 1024)

__global__ __launch_bounds__(256, 2) void gemm_bf16x3(
    const float* __restrict__ A,      // [16384, 512] f32
    const float* __restrict__ bias)
{
    extern __shared__ char dsm[];
    const uint32_t raw = smem_u32(dsm);
    const uint32_t sb = (raw + 1023u) & ~1023u;
    char* smp = dsm + (sb - raw);

    const int tid = threadIdx.x;
    const int wid = tid >> 5, lane = tid & 31;
    const int rowBase = blockIdx.y * 128;
    const int colBase = blockIdx.x * 64;
    const int warpM = (wid & 3) * 32;        // 4 warps over M=128
    const int warpN = (wid >> 2) * 32;       // 2 warps over N=64

    const __nv_bfloat16* __restrict__ Bh = g_Wt_hi;
    const __nv_bfloat16* __restrict__ Bl = g_Wt_lo;

    // B load coords: 64 rows x 4 units -> 256 chunks, 1/thread per matrix
    const int rb = tid >> 2, cb = tid & 3;

    auto load_stage = [&](int ck) {
        const uint32_t so = sb + (ck & 3) * STAGE_BYTES;
        const int kt = ck * 32;
        // A f32: 128 rows x 8 units(16B) = 1024 chunks, 4/thread
        #pragma unroll
        for (int l = 0; l < 4; l++) {
            int ch = tid + 256 * l;
            int row = ch >> 3, u = ch & 7;
            CP_ASYNC16(so + AF_OFF + SW128((uint32_t)(row * 128 + u * 16)),
                       &A[(size_t)(rowBase + row) * Hd + kt + u * 4]);
        }
        const uint32_t offB = SW64((uint32_t)(rb * 64 + cb * 16));
        CP_ASYNC16(so + BHI_OFF + offB, &Bh[(size_t)(colBase + rb) * Hd + kt + cb * 8]);
        CP_ASYNC16(so + BLO_OFF + offB, &Bl[(size_t)(colBase + rb) * Hd + kt + cb * 8]);
    };

    float c[2][4][4];
    #pragma unroll
    for (int i = 0; i < 2; i++)
        #pragma unroll
        for (int j = 0; j < 4; j++)
            #pragma unroll
            for (int k = 0; k < 4; k++) c[i][j][k] = 0.0f;

    const uint32_t a_row = warpM + (lane & 15);
    const uint32_t a_colpart = (lane >> 4) * 16;
    const uint32_t b_row = warpN + ((lane >> 4) ? 8u : 0u) + (lane & 7);
    const uint32_t b_colpart = ((lane >> 3) & 1) * 16;

    // conversion coords: thread -> (row, half)
    const int cr = tid >> 1, chf = tid & 1;
    uint32_t cvtL[4], cvtS0, cvtS1;
    #pragma unroll
    for (int j = 0; j < 4; j++)
        cvtL[j] = SW128((uint32_t)(cr * 128 + chf * 64 + j * 16));
    cvtS0 = SW64((uint32_t)(cr * 64 + chf * 32));
    cvtS1 = SW64((uint32_t)(cr * 64 + chf * 32 + 16));

    load_stage(0); CP_COMMIT();
    load_stage(1); CP_COMMIT();
    load_stage(2); CP_COMMIT();

    for (int ck = 0; ck < NCHUNK; ck++) {
        CP_WAIT2();
        __syncthreads();
        if (ck + 3 < NCHUNK) load_stage(ck + 3);
        CP_COMMIT();

        const uint32_t so = sb + (ck & 3) * STAGE_BYTES;
        char* stp = smp + (ck & 3) * STAGE_BYTES;

        // ---- in-stage A conversion: f32 -> bf16 hi/lo over same 16KB ----
        float4 f[4];
        #pragma unroll
        for (int j = 0; j < 4; j++)
            f[j] = *reinterpret_cast<const float4*>(stp + AF_OFF + cvtL[j]);
        __syncthreads();                       // all reads before overwrite
        uint32_t hp[8], lp[8];
        #pragma unroll
        for (int j = 0; j < 4; j++) {
            split2(f[j].x, f[j].y, hp[2*j],   lp[2*j]);
            split2(f[j].z, f[j].w, hp[2*j+1], lp[2*j+1]);
        }
        *reinterpret_cast<uint4*>(stp + AHI_OFF + cvtS0) = make_uint4(hp[0], hp[1], hp[2], hp[3]);
        *reinterpret_cast<uint4*>(stp + AHI_OFF + cvtS1) = make_uint4(hp[4], hp[5], hp[6], hp[7]);
        *reinterpret_cast<uint4*>(stp + ALO_OFF + cvtS0) = make_uint4(lp[0], lp[1], lp[2], lp[3]);
        *reinterpret_cast<uint4*>(stp + ALO_OFF + cvtS1) = make_uint4(lp[4], lp[5], lp[6], lp[7]);
        __syncthreads();                       // bf16 visible before ldmatrix

        #pragma unroll
        for (int kk = 0; kk < 32; kk += 16) {
            uint32_t ah[2][4], al[2][4], bh[4][2], bl[4][2];
            uint32_t aoff[2], boff[2];
            #pragma unroll
            for (int ma = 0; ma < 2; ma++)
                aoff[ma] = SW64((a_row + ma * 16) * 64 + kk * 2 + a_colpart);
            #pragma unroll
            for (int p = 0; p < 2; p++)
                boff[p] = SW64((b_row + p * 16) * 64 + kk * 2 + b_colpart);

            // group 1: bh + ah, then hh MMAs
            #pragma unroll
            for (int p = 0; p < 2; p++) {
                uint32_t q0, q1, q2, q3;
                LDSM_X4(q0, q1, q2, q3, so + BHI_OFF + boff[p]);
                bh[2*p][0] = q0; bh[2*p][1] = q1; bh[2*p+1][0] = q2; bh[2*p+1][1] = q3;
            }
            #pragma unroll
            for (int ma = 0; ma < 2; ma++)
                LDSM_X4(ah[ma][0], ah[ma][1], ah[ma][2], ah[ma][3], so + AHI_OFF + aoff[ma]);
            #pragma unroll
            for (int ma = 0; ma < 2; ma++)
                #pragma unroll
                for (int nb = 0; nb < 4; nb++) MMA_BF16(c[ma][nb], ah[ma], bh[nb]);

            // group 2: al, then lh MMAs
            #pragma unroll
            for (int ma = 0; ma < 2; ma++)
                LDSM_X4(al[ma][0], al[ma][1], al[ma][2], al[ma][3], so + ALO_OFF + aoff[ma]);
            #pragma unroll
            for (int ma = 0; ma < 2; ma++)
                #pragma unroll
                for (int nb = 0; nb < 4; nb++) MMA_BF16(c[ma][nb], al[ma], bh[nb]);

            // group 3: bl, then hl MMAs
            #pragma unroll
            for (int p = 0; p < 2; p++) {
                uint32_t q0, q1, q2, q3;
                LDSM_X4(q0, q1, q2, q3, so + BLO_OFF + boff[p]);
                bl[2*p][0] = q0; bl[2*p][1] = q1; bl[2*p+1][0] = q2; bl[2*p+1][1] = q3;
            }
            #pragma unroll
            for (int ma = 0; ma < 2; ma++)
                #pragma unroll
                for (int nb = 0; nb < 4; nb++) MMA_BF16(c[ma][nb], ah[ma], bl[nb]);
        }
    }
    CP_WAIT0();

    // Epilogue
    float bv[8];
    #pragma unroll
    for (int nb = 0; nb < 4; nb++) {
        int cc = colBase + warpN + nb * 8 + (lane & 3) * 2;
        bv[2*nb]   = bias[cc];
        bv[2*nb+1] = bias[cc + 1];
    }
    #pragma unroll
    for (int ma = 0; ma < 2; ma++) {
        int rr0 = rowBase + warpM + ma * 16 + (lane >> 2);
        #pragma unroll
        for (int nb = 0; nb < 4; nb++) {
            int cc = colBase + warpN + nb * 8 + (lane & 3) * 2;
            float2 v0 = make_float2(c[ma][nb][0] + bv[2*nb], c[ma][nb][1] + bv[2*nb+1]);
            float2 v1 = make_float2(c[ma][nb][2] + bv[2*nb], c[ma][nb][3] + bv[2*nb+1]);
            *reinterpret_cast<float2*>(&g_logits[(size_t)rr0 * GVc + cc]) = v0;
            *reinterpret_cast<float2*>(&g_logits[(size_t)(rr0 + 8) * GVc + cc]) = v1;
        }
    }
}

// ---------------------------------------------------------------------------
// Rows: one warp per (n,g): argmax(l+g) gather + masked softmax marginal.
// Softmax math skipped entirely for unmasked rows.
// ---------------------------------------------------------------------------
#define RPB 32

__global__ __launch_bounds__(256) void rows_kernel(
    const float* __restrict__ gumbels,
    const int*   __restrict__ mask,
    const float* __restrict__ codevectors,
    float*       __restrict__ out)
{
    __shared__ float sAcc[GVc];
    const int tid = threadIdx.x, lane = tid & 31, warp = tid >> 5;

    for (int i = tid; i < GVc; i += 256) sAcc[i] = 0.0f;
    __syncthreads();

    const int base = blockIdx.x * RPB;
    for (int rr = warp; rr < RPB; rr += 8) {
        const int row = base + rr;
        const int n = row >> 1, g = row & 1;
        const float* lrow = &g_logits[(size_t)n * GVc + g * Vv];
        const float* grow = &gumbels[(size_t)row * Vv];
        const bool m = (mask[n] != 0);

        float lv[10];
        float bestv = -1e30f; int besti = 0;
        #pragma unroll
        for (int t = 0; t < 10; t++) {
            int v = lane + 32 * t;
            float x = lrow[v];
            lv[t] = x;
            float s = x + grow[v];
            if (s > bestv) { bestv = s; besti = v; }
        }
        #pragma unroll
        for (int off = 16; off; off >>= 1) {
            float ov = __shfl_xor_sync(0xffffffffu, bestv, off);
            int   oi = __shfl_xor_sync(0xffffffffu, besti, off);
            if (ov > bestv || (ov == bestv && oi < besti)) { bestv = ov; besti = oi; }
        }

        if (m) {
            float mx = -1e30f;
            #pragma unroll
            for (int t = 0; t < 10; t++) mx = fmaxf(mx, lv[t]);
            #pragma unroll
            for (int off = 16; off; off >>= 1)
                mx = fmaxf(mx, __shfl_xor_sync(0xffffffffu, mx, off));
            float ev[10], sum = 0.0f;
            #pragma unroll
            for (int t = 0; t < 10; t++) { ev[t] = __expf(lv[t] - mx); sum += ev[t]; }
            #pragma unroll
            for (int off = 16; off; off >>= 1) sum += __shfl_xor_sync(0xffffffffu, sum, off);
            const float inv = 1.0f / sum;
            #pragma unroll
            for (int t = 0; t < 10; t++)
                atomicAdd(&sAcc[g * Vv + lane + 32 * t], ev[t] * inv);
        }

        const float4* src = reinterpret_cast<const float4*>(
            &codevectors[((size_t)g * Vv + besti) * (Dd / Gg)]);
        float4* dst = reinterpret_cast<float4*>(&out[(size_t)n * Dd + g * (Dd / Gg)]);
        dst[lane] = src[lane];
    }
    __syncthreads();
    for (int i = tid; i < GVc; i += 256) atomicAdd(&g_acc[i], sAcc[i]);
}

// ---------------------------------------------------------------------------
// Finalize: mask count + perplexity (640 threads, deterministic)
// ---------------------------------------------------------------------------
__global__ __launch_bounds__(640) void finalize_kernel(
    const int* __restrict__ mask, float* __restrict__ out, int out_size)
{
    __shared__ float  mred[640];
    __shared__ double wsum[20];
    const int tid = threadIdx.x, lane = tid & 31, warp = tid >> 5;

    float cnt = 0.0f;
    for (int i = tid; i < Nrows / 4; i += 640) {
        int4 m = reinterpret_cast<const int4*>(mask)[i];
        cnt += (m.x != 0) + (m.y != 0) + (m.z != 0) + (m.w != 0);
    }
    #pragma unroll
    for (int off = 16; off; off >>= 1) cnt += __shfl_xor_sync(0xffffffffu, cnt, off);
    if (lane == 0) mred[warp] = cnt;
    __syncthreads();
    double msum = 0.0;
    for (int w = 0; w < 20; w++) msum += (double)mred[w];

    double marg = (double)g_acc[tid] / msum;
    double t = marg * log(marg + 1e-7);
    #pragma unroll
    for (int off = 16; off; off >>= 1)
        t += __shfl_xor_sync(0xffffffffu, t, off);
    if (lane == 0) wsum[warp] = t;
    __syncthreads();
    if (tid == 0) {
        double e0 = 0.0, e1 = 0.0;
        for (int w = 0; w < 10; w++)  e0 += wsum[w];
        for (int w = 10; w < 20; w++) e1 += wsum[w];
        out[out_size - 1] = (float)(exp(-e0) + exp(-e1));
    }
}

// ---------------------------------------------------------------------------
extern "C" void kernel_launch(void* const* d_in, const int* in_sizes, int n_in,
                              void* d_out, int out_size)
{
    (void)in_sizes; (void)n_in;
    const float* hs   = (const float*)d_in[0];
    const int*   mask = (const int*)  d_in[1];
    const float* W    = (const float*)d_in[2];
    const float* bias = (const float*)d_in[3];
    const float* cb   = (const float*)d_in[4];
    const float* gmb  = (const float*)d_in[5];
    float* out = (float*)d_out;

    static bool attr_set = false;
    if (!attr_set) {
        cudaFuncSetAttribute(gemm_bf16x3, cudaFuncAttributeMaxDynamicSharedMemorySize, GEMM_SMEM);
        attr_set = true;
    }

    prep_W<<<(Hd * GVc) / 256, 256>>>(W);

    dim3 ggrid(GVc / 64, Nrows / 128);   // (10, 128) = 1280 CTAs
    gemm_bf16x3<<<ggrid, 256, GEMM_SMEM>>>(hs, bias);

    rows_kernel<<<(Nrows * Gg) / RPB, 256>>>(gmb, mask, cb, out);
    finalize_kernel<<<1, 640>>>(mask, out, out_size);
}